// round 1
// baseline (speedup 1.0000x reference)
#include <cuda_runtime.h>
#include <math.h>

#define NS 128
#define NV 64
#define FSZ 320            // NS + 3*NV
#define TE 32              // edges (or nodes) per block

// LN'd node features scratch (N up to 16000)
__device__ float g_nodeN[16000 * FSZ];

// ---------------------------------------------------------------------------
// Kernel A: per-node separable LN -> g_nodeN, residual (raw @ Wr_s / Wr_v) -> out
// ---------------------------------------------------------------------------
__global__ __launch_bounds__(256) void node_kernel(
    const float* __restrict__ nf,
    const float* __restrict__ g_s_n, const float* __restrict__ b_s_n,
    const float* __restrict__ g_v_n,
    const float* __restrict__ Wr_s, const float* __restrict__ Wr_v,
    float* __restrict__ out, int N)
{
    __shared__ float rs_raw[TE * 128];      // raw scalars
    __shared__ float rv_raw[3 * TE * 64];   // raw vectors [d][node][c]

    int tid = threadIdx.x;
    {
        int e = tid >> 3, j = tid & 7;
        int n = blockIdx.x * TE + e;
        bool valid = n < N;

        // scalar LN
        float xr[16]; float sum = 0.f, sq = 0.f;
        #pragma unroll
        for (int t = 0; t < 16; t++) {
            int k = j + t * 8;
            float x = valid ? nf[n * FSZ + k] : 0.f;
            xr[t] = x; rs_raw[e * 128 + k] = x;
            sum += x; sq += x * x;
        }
        #pragma unroll
        for (int m = 1; m < 8; m <<= 1) {
            sum += __shfl_xor_sync(0xffffffffu, sum, m, 8);
            sq  += __shfl_xor_sync(0xffffffffu, sq,  m, 8);
        }
        float mu  = sum * (1.f / 128.f);
        float var = sq * (1.f / 128.f) - mu * mu;
        float inv = rsqrtf(var + 1e-5f);
        if (valid) {
            #pragma unroll
            for (int t = 0; t < 16; t++) {
                int k = j + t * 8;
                g_nodeN[n * FSZ + k] = (xr[t] - mu) * inv * __ldg(g_s_n + k) + __ldg(b_s_n + k);
            }
        }
        // vector LN
        float vr[8][3]; float vq = 0.f;
        #pragma unroll
        for (int t = 0; t < 8; t++) {
            int c = j + t * 8;
            #pragma unroll
            for (int d = 0; d < 3; d++) {
                float x = valid ? nf[n * FSZ + 128 + c * 3 + d] : 0.f;
                vr[t][d] = x; rv_raw[(d * TE + e) * 64 + c] = x;
                vq += x * x;
            }
        }
        #pragma unroll
        for (int m = 1; m < 8; m <<= 1) vq += __shfl_xor_sync(0xffffffffu, vq, m, 8);
        float vinv = rsqrtf(vq * (1.f / 64.f) + 1e-5f);
        if (valid) {
            #pragma unroll
            for (int t = 0; t < 8; t++) {
                int c = j + t * 8; float g = __ldg(g_v_n + c);
                #pragma unroll
                for (int d = 0; d < 3; d++)
                    g_nodeN[n * FSZ + 128 + c * 3 + d] = vr[t][d] * vinv * g;
            }
        }
    }
    __syncthreads();

    // residual scalars: out[n][c] = sum_k raw_s[k] * Wr_s[k][c]
    {
        int tc = tid & 31, te = tid >> 5;
        int c0 = tc * 4;
        float acc[4][4] = {};
        for (int k = 0; k < 128; k++) {
            float4 w = __ldg(reinterpret_cast<const float4*>(&Wr_s[k * 128 + c0]));
            #pragma unroll
            for (int i = 0; i < 4; i++) {
                float a = rs_raw[(te * 4 + i) * 128 + k];
                acc[i][0] += a * w.x; acc[i][1] += a * w.y;
                acc[i][2] += a * w.z; acc[i][3] += a * w.w;
            }
        }
        #pragma unroll
        for (int i = 0; i < 4; i++) {
            int nn = blockIdx.x * TE + te * 4 + i;
            if (nn < N) {
                #pragma unroll
                for (int u = 0; u < 4; u++) out[(long)nn * FSZ + c0 + u] = acc[i][u];
            }
        }
    }
    // residual vectors: out[n][128+f*3+d] = sum_c raw_v[c][d] * Wr_v[c][f]
    {
        int tf = tid & 31, te = tid >> 5;
        int f0 = tf * 2;
        float acc[4][2][3] = {};
        for (int c = 0; c < 64; c++) {
            float2 w = __ldg(reinterpret_cast<const float2*>(&Wr_v[c * 64 + f0]));
            #pragma unroll
            for (int i = 0; i < 4; i++) {
                int ee = te * 4 + i;
                #pragma unroll
                for (int d = 0; d < 3; d++) {
                    float v = rv_raw[(d * TE + ee) * 64 + c];
                    acc[i][0][d] += v * w.x; acc[i][1][d] += v * w.y;
                }
            }
        }
        #pragma unroll
        for (int i = 0; i < 4; i++) {
            int nn = blockIdx.x * TE + te * 4 + i;
            if (nn < N) {
                #pragma unroll
                for (int u = 0; u < 2; u++)
                    #pragma unroll
                    for (int d = 0; d < 3; d++)
                        out[(long)nn * FSZ + 128 + (f0 + u) * 3 + d] = acc[i][u][d];
            }
        }
    }
}

// ---------------------------------------------------------------------------
// Kernel B: fused per-edge pipeline, 32 edges per CTA, atomicAdd into out
// ---------------------------------------------------------------------------
// smem layout (floats):
//   S   [0,8192)      : S[e][k], k<256  (aliased by WW=w[e][192] in phase>=3)
//   V   [8192,20480)  : V[(d*32+e)*128+c]
//   CR  [20480,32768) : cross, same layout
//   DV  [32768,36864) : dotV[e*128+c]
//   OG  [36864,43008) : out0 post-activation: sact[e][m<128], gates[e][128..191]
//   VP  [43008,49152) : gated out_v: VP[(d*32+e)*64+f]
//   SH  [49152,49280) : edge_sh[e][4]
//   EC/AE ints after
#define SMEM_FLOATS 49280
#define SMEM_BYTES  (SMEM_FLOATS * 4 + 2 * TE * 4)

__global__ __launch_bounds__(256, 1) void edge_kernel(
    const float* __restrict__ latents,
    const float* __restrict__ ef,
    const float* __restrict__ esh,
    const int*  __restrict__ edge_index,
    const int*  __restrict__ active_edges,
    const float* __restrict__ g_s_e, const float* __restrict__ b_s_e,
    const float* __restrict__ g_v_e,
    const float* __restrict__ W_ss0, const float* __restrict__ W_vv0,
    const float* __restrict__ W_sv1, const float* __restrict__ W_vs1,
    const float* __restrict__ W_vv1,
    const float* __restrict__ Wp_s,  const float* __restrict__ Wp_v,
    const float* __restrict__ W_env,
    float* __restrict__ out, int EA)
{
    extern __shared__ float sm[];
    float* S  = sm;
    float* V  = sm + 8192;
    float* CR = sm + 20480;
    float* DV = sm + 32768;
    float* OG = sm + 36864;
    float* VP = sm + 43008;
    float* SH = sm + 49152;
    int*   EC = (int*)(sm + SMEM_FLOATS);
    int*   AE = EC + TE;
    float* WW = S;   // alias: env weights w[e][192], live phase >= 3

    int tid = threadIdx.x;

    // ---------------- Phase 0: load + LN + gather + dot/cross ----------------
    {
        int e = tid >> 3, j = tid & 7;
        long i = (long)blockIdx.x * TE + e;
        bool valid = i < EA;
        int ae = 0, n = 0;
        if (valid) { ae = active_edges[i]; n = edge_index[ae]; }
        if (j == 0) {
            EC[e] = valid ? n : -1;
            AE[e] = ae;
            #pragma unroll
            for (int q = 0; q < 4; q++) SH[e * 4 + q] = valid ? esh[i * 4 + q] : 0.f;
        }
        // edge scalar LN
        float xr[16]; float sum = 0.f, sq = 0.f;
        #pragma unroll
        for (int t = 0; t < 16; t++) {
            int k = j + t * 8;
            float x = valid ? ef[i * FSZ + k] : 0.f;
            xr[t] = x; sum += x; sq += x * x;
        }
        #pragma unroll
        for (int m = 1; m < 8; m <<= 1) {
            sum += __shfl_xor_sync(0xffffffffu, sum, m, 8);
            sq  += __shfl_xor_sync(0xffffffffu, sq,  m, 8);
        }
        float mu  = sum * (1.f / 128.f);
        float var = sq * (1.f / 128.f) - mu * mu;
        float inv = rsqrtf(var + 1e-5f);
        #pragma unroll
        for (int t = 0; t < 16; t++) {
            int k = j + t * 8;
            float v = (xr[t] - mu) * inv * __ldg(g_s_e + k) + __ldg(b_s_e + k);
            S[e * 256 + 128 + k] = valid ? v : 0.f;
        }
        // edge vector LN
        float vr[8][3]; float vq = 0.f;
        #pragma unroll
        for (int t = 0; t < 8; t++) {
            int c = j + t * 8;
            #pragma unroll
            for (int d = 0; d < 3; d++) {
                float x = valid ? ef[i * FSZ + 128 + c * 3 + d] : 0.f;
                vr[t][d] = x; vq += x * x;
            }
        }
        #pragma unroll
        for (int m = 1; m < 8; m <<= 1) vq += __shfl_xor_sync(0xffffffffu, vq, m, 8);
        float vinv = rsqrtf(vq * (1.f / 64.f) + 1e-5f);
        #pragma unroll
        for (int t = 0; t < 8; t++) {
            int c = j + t * 8; float g = __ldg(g_v_e + c);
            #pragma unroll
            for (int d = 0; d < 3; d++)
                V[(d * TE + e) * 128 + 64 + c] = valid ? vr[t][d] * vinv * g : 0.f;
        }
        // gather LN'd source-node features
        #pragma unroll
        for (int t = 0; t < 16; t++) {
            int k = j + t * 8;
            S[e * 256 + k] = valid ? __ldg(&g_nodeN[(long)n * FSZ + k]) : 0.f;
        }
        #pragma unroll
        for (int t = 0; t < 8; t++) {
            int c = j + t * 8;
            #pragma unroll
            for (int d = 0; d < 3; d++)
                V[(d * TE + e) * 128 + c] = valid ? __ldg(&g_nodeN[(long)n * FSZ + 128 + c * 3 + d]) : 0.f;
        }
        __syncwarp();
        // dot and cross with sh1 (includes 1/sqrt3, 1/sqrt2 factors)
        float s1x = SH[e * 4 + 1], s1y = SH[e * 4 + 2], s1z = SH[e * 4 + 3];
        #pragma unroll
        for (int t = 0; t < 16; t++) {
            int c = j + t * 8;
            float vx = V[(0 * TE + e) * 128 + c];
            float vy = V[(1 * TE + e) * 128 + c];
            float vz = V[(2 * TE + e) * 128 + c];
            DV[e * 128 + c] = (vx * s1x + vy * s1y + vz * s1z) * 0.5773502691896258f;
            CR[(0 * TE + e) * 128 + c] = (vy * s1z - vz * s1y) * 0.7071067811865476f;
            CR[(1 * TE + e) * 128 + c] = (vz * s1x - vx * s1z) * 0.7071067811865476f;
            CR[(2 * TE + e) * 128 + c] = (vx * s1y - vy * s1x) * 0.7071067811865476f;
        }
    }
    __syncthreads();

    // ---------------- Phase 1: out0 = (S@W_ss0)*sh0 + DV@W_vv0 ; silu/sigmoid --
    {
        int tc = tid & 31, te = tid >> 5;
        int c0 = tc * 6;
        float acc[4][6] = {};
        #pragma unroll 2
        for (int k = 0; k < 256; k++) {
            const float* wr = &W_ss0[k * 192 + c0];
            float2 w01 = __ldg(reinterpret_cast<const float2*>(wr));
            float2 w23 = __ldg(reinterpret_cast<const float2*>(wr + 2));
            float2 w45 = __ldg(reinterpret_cast<const float2*>(wr + 4));
            #pragma unroll
            for (int i = 0; i < 4; i++) {
                float a = S[(te * 4 + i) * 256 + k];
                acc[i][0] += a * w01.x; acc[i][1] += a * w01.y;
                acc[i][2] += a * w23.x; acc[i][3] += a * w23.y;
                acc[i][4] += a * w45.x; acc[i][5] += a * w45.y;
            }
        }
        #pragma unroll
        for (int i = 0; i < 4; i++) {
            float s0 = SH[(te * 4 + i) * 4];
            #pragma unroll
            for (int u = 0; u < 6; u++) acc[i][u] *= s0;
        }
        #pragma unroll 2
        for (int k = 0; k < 128; k++) {
            const float* wr = &W_vv0[k * 192 + c0];
            float2 w01 = __ldg(reinterpret_cast<const float2*>(wr));
            float2 w23 = __ldg(reinterpret_cast<const float2*>(wr + 2));
            float2 w45 = __ldg(reinterpret_cast<const float2*>(wr + 4));
            #pragma unroll
            for (int i = 0; i < 4; i++) {
                float a = DV[(te * 4 + i) * 128 + k];
                acc[i][0] += a * w01.x; acc[i][1] += a * w01.y;
                acc[i][2] += a * w23.x; acc[i][3] += a * w23.y;
                acc[i][4] += a * w45.x; acc[i][5] += a * w45.y;
            }
        }
        #pragma unroll
        for (int i = 0; i < 4; i++) {
            int e = te * 4 + i;
            #pragma unroll
            for (int u = 0; u < 6; u++) {
                int m = c0 + u; float x = acc[i][u];
                float sg = 1.f / (1.f + expf(-x));
                OG[e * 192 + m] = (m < 128) ? x * sg : sg;
            }
        }
    }
    __syncthreads();

    // ---------------- Phase 2: out_v, gate, -> VP -----------------------------
    {
        int tf = tid & 31, te = tid >> 5;
        int f0 = tf * 2;
        float aS[4][2] = {};
        #pragma unroll 2
        for (int k = 0; k < 256; k++) {
            float2 w = __ldg(reinterpret_cast<const float2*>(&W_sv1[k * 64 + f0]));
            #pragma unroll
            for (int i = 0; i < 4; i++) {
                float a = S[(te * 4 + i) * 256 + k];
                aS[i][0] += a * w.x; aS[i][1] += a * w.y;
            }
        }
        float aV[4][2][3] = {}, aC[4][2][3] = {};
        #pragma unroll 2
        for (int c = 0; c < 128; c++) {
            float2 wv = __ldg(reinterpret_cast<const float2*>(&W_vs1[c * 64 + f0]));
            float2 wc = __ldg(reinterpret_cast<const float2*>(&W_vv1[c * 64 + f0]));
            #pragma unroll
            for (int i = 0; i < 4; i++) {
                int e = te * 4 + i;
                #pragma unroll
                for (int d = 0; d < 3; d++) {
                    float v  = V[(d * TE + e) * 128 + c];
                    float cr = CR[(d * TE + e) * 128 + c];
                    aV[i][0][d] += v * wv.x;  aV[i][1][d] += v * wv.y;
                    aC[i][0][d] += cr * wc.x; aC[i][1][d] += cr * wc.y;
                }
            }
        }
        #pragma unroll
        for (int i = 0; i < 4; i++) {
            int e = te * 4 + i;
            float s0 = SH[e * 4];
            float s1[3] = { SH[e * 4 + 1], SH[e * 4 + 2], SH[e * 4 + 3] };
            #pragma unroll
            for (int u = 0; u < 2; u++) {
                float g = OG[e * 192 + 128 + f0 + u];
                #pragma unroll
                for (int d = 0; d < 3; d++)
                    VP[(d * TE + e) * 64 + f0 + u] =
                        (aS[i][u] * s1[d] + aV[i][u][d] * s0 + aC[i][u][d]) * g;
            }
        }
    }
    __syncthreads();

    // ---------------- Phase 3: w = latents[ae] @ W_env -> WW (aliases S) ------
    {
        int tc = tid & 31, te = tid >> 5;
        int c0 = tc * 6;
        int ae_[4];
        #pragma unroll
        for (int i = 0; i < 4; i++) ae_[i] = AE[te * 4 + i];
        float acc[4][6] = {};
        #pragma unroll 2
        for (int k = 0; k < 64; k++) {
            const float* wr = &W_env[k * 192 + c0];
            float2 w01 = __ldg(reinterpret_cast<const float2*>(wr));
            float2 w23 = __ldg(reinterpret_cast<const float2*>(wr + 2));
            float2 w45 = __ldg(reinterpret_cast<const float2*>(wr + 4));
            #pragma unroll
            for (int i = 0; i < 4; i++) {
                float a = __ldg(&latents[(long)ae_[i] * 64 + k]);
                acc[i][0] += a * w01.x; acc[i][1] += a * w01.y;
                acc[i][2] += a * w23.x; acc[i][3] += a * w23.y;
                acc[i][4] += a * w45.x; acc[i][5] += a * w45.y;
            }
        }
        #pragma unroll
        for (int i = 0; i < 4; i++)
            #pragma unroll
            for (int u = 0; u < 6; u++)
                WW[(te * 4 + i) * 192 + c0 + u] = acc[i][u];
    }
    __syncthreads();

    // ---------------- Phase 4a: s = (sact@Wp_s)*w_s*0.25 -> atomicAdd ---------
    {
        int tc = tid & 31, te = tid >> 5;
        int c0 = tc * 4;
        float acc[4][4] = {};
        #pragma unroll 2
        for (int k = 0; k < 128; k++) {
            float4 w = __ldg(reinterpret_cast<const float4*>(&Wp_s[k * 128 + c0]));
            #pragma unroll
            for (int i = 0; i < 4; i++) {
                float a = OG[(te * 4 + i) * 192 + k];
                acc[i][0] += a * w.x; acc[i][1] += a * w.y;
                acc[i][2] += a * w.z; acc[i][3] += a * w.w;
            }
        }
        #pragma unroll
        for (int i = 0; i < 4; i++) {
            int e = te * 4 + i; int n = EC[e];
            if (n >= 0) {
                #pragma unroll
                for (int u = 0; u < 4; u++) {
                    float val = acc[i][u] * WW[e * 192 + c0 + u] * 0.25f;
                    atomicAdd(&out[(long)n * FSZ + c0 + u], val);
                }
            }
        }
    }
    // ---------------- Phase 4b: v = (VP@Wp_v)*w_v*0.25 -> atomicAdd -----------
    {
        int tf = tid & 31, te = tid >> 5;
        int f0 = tf * 2;
        float acc[4][2][3] = {};
        #pragma unroll 2
        for (int c = 0; c < 64; c++) {
            float2 w = __ldg(reinterpret_cast<const float2*>(&Wp_v[c * 64 + f0]));
            #pragma unroll
            for (int i = 0; i < 4; i++) {
                int e = te * 4 + i;
                #pragma unroll
                for (int d = 0; d < 3; d++) {
                    float v = VP[(d * TE + e) * 64 + c];
                    acc[i][0][d] += v * w.x; acc[i][1][d] += v * w.y;
                }
            }
        }
        #pragma unroll
        for (int i = 0; i < 4; i++) {
            int e = te * 4 + i; int n = EC[e];
            if (n >= 0) {
                #pragma unroll
                for (int u = 0; u < 2; u++) {
                    float wv = WW[e * 192 + 128 + f0 + u] * 0.25f;
                    #pragma unroll
                    for (int d = 0; d < 3; d++)
                        atomicAdd(&out[(long)n * FSZ + 128 + (f0 + u) * 3 + d],
                                  acc[i][u][d] * wv);
                }
            }
        }
    }
}

// ---------------------------------------------------------------------------
extern "C" void kernel_launch(void* const* d_in, const int* in_sizes, int n_in,
                              void* d_out, int out_size)
{
    const float* latents = (const float*)d_in[0];
    const float* nodef   = (const float*)d_in[1];
    const float* edgef   = (const float*)d_in[2];
    const float* esh     = (const float*)d_in[3];
    const int*   eidx    = (const int*)  d_in[4];
    // d_in[5] = atom_type (unused)
    const int*   act     = (const int*)  d_in[6];
    const float* g_s_n   = (const float*)d_in[7];
    const float* b_s_n   = (const float*)d_in[8];
    const float* g_v_n   = (const float*)d_in[9];
    const float* g_s_e   = (const float*)d_in[10];
    const float* b_s_e   = (const float*)d_in[11];
    const float* g_v_e   = (const float*)d_in[12];
    const float* W_ss0   = (const float*)d_in[13];
    const float* W_vv0   = (const float*)d_in[14];
    const float* W_sv1   = (const float*)d_in[15];
    const float* W_vs1   = (const float*)d_in[16];
    const float* W_vv1   = (const float*)d_in[17];
    const float* Wp_s    = (const float*)d_in[18];
    const float* Wp_v    = (const float*)d_in[19];
    const float* W_env   = (const float*)d_in[20];
    const float* Wr_s    = (const float*)d_in[21];
    const float* Wr_v    = (const float*)d_in[22];
    float* out = (float*)d_out;

    int N  = in_sizes[1] / FSZ;
    int EA = in_sizes[6];

    cudaFuncSetAttribute(edge_kernel, cudaFuncAttributeMaxDynamicSharedMemorySize,
                         SMEM_BYTES);

    node_kernel<<<(N + TE - 1) / TE, 256>>>(nodef, g_s_n, b_s_n, g_v_n,
                                            Wr_s, Wr_v, out, N);
    edge_kernel<<<(EA + TE - 1) / TE, 256, SMEM_BYTES>>>(
        latents, edgef, esh, eidx, act,
        g_s_e, b_s_e, g_v_e,
        W_ss0, W_vv0, W_sv1, W_vs1, W_vv1,
        Wp_s, Wp_v, W_env, out, EA);
}

// round 3
// speedup vs baseline: 1.1271x; 1.1271x over previous
#include <cuda_runtime.h>
#include <math.h>

#define NS 128
#define NV 64
#define FSZ 320            // NS + 3*NV
#define TE 32              // edges per block (edge kernel), nodes per block (node kernel)

typedef unsigned long long ull;

__device__ __forceinline__ ull pk2(float lo, float hi) {
    ull r; asm("mov.b64 %0,{%1,%2};" : "=l"(r) : "f"(lo), "f"(hi)); return r;
}
__device__ __forceinline__ void upk2(ull v, float& lo, float& hi) {
    asm("mov.b64 {%0,%1},%2;" : "=f"(lo), "=f"(hi) : "l"(v));
}
__device__ __forceinline__ void fma2(ull& d, ull a, ull b) {
    asm("fma.rn.f32x2 %0,%1,%2,%0;" : "+l"(d) : "l"(a), "l"(b));
}
__device__ __forceinline__ ull fma2v(ull a, ull b, ull c) {
    ull d; asm("fma.rn.f32x2 %0,%1,%2,%3;" : "=l"(d) : "l"(a), "l"(b), "l"(c)); return d;
}
__device__ __forceinline__ ull mul2(ull a, ull b) {
    ull d; asm("mul.rn.f32x2 %0,%1,%2;" : "=l"(d) : "l"(a), "l"(b)); return d;
}

// LN'd node features scratch
__device__ float g_nodeN[16000 * FSZ];

// ---------------------------------------------------------------------------
// Kernel A: per-node separable LN -> g_nodeN, residual (raw @ Wr_s / Wr_v) -> out
// ---------------------------------------------------------------------------
__global__ __launch_bounds__(256) void node_kernel(
    const float* __restrict__ nf,
    const float* __restrict__ g_s_n, const float* __restrict__ b_s_n,
    const float* __restrict__ g_v_n,
    const float* __restrict__ Wr_s, const float* __restrict__ Wr_v,
    float* __restrict__ out, int N)
{
    __shared__ float rs_raw[TE * 128];
    __shared__ float rv_raw[3 * TE * 64];

    int tid = threadIdx.x;
    {
        int e = tid >> 3, j = tid & 7;
        int n = blockIdx.x * TE + e;
        bool valid = n < N;

        float xr[16]; float sum = 0.f, sq = 0.f;
        #pragma unroll
        for (int t = 0; t < 16; t++) {
            int k = j + t * 8;
            float x = valid ? nf[n * FSZ + k] : 0.f;
            xr[t] = x; rs_raw[e * 128 + k] = x;
            sum += x; sq += x * x;
        }
        #pragma unroll
        for (int m = 1; m < 8; m <<= 1) {
            sum += __shfl_xor_sync(0xffffffffu, sum, m, 8);
            sq  += __shfl_xor_sync(0xffffffffu, sq,  m, 8);
        }
        float mu  = sum * (1.f / 128.f);
        float var = sq * (1.f / 128.f) - mu * mu;
        float inv = rsqrtf(var + 1e-5f);
        if (valid) {
            #pragma unroll
            for (int t = 0; t < 16; t++) {
                int k = j + t * 8;
                g_nodeN[n * FSZ + k] = (xr[t] - mu) * inv * __ldg(g_s_n + k) + __ldg(b_s_n + k);
            }
        }
        float vr[8][3]; float vq = 0.f;
        #pragma unroll
        for (int t = 0; t < 8; t++) {
            int c = j + t * 8;
            #pragma unroll
            for (int d = 0; d < 3; d++) {
                float x = valid ? nf[n * FSZ + 128 + c * 3 + d] : 0.f;
                vr[t][d] = x; rv_raw[(d * TE + e) * 64 + c] = x;
                vq += x * x;
            }
        }
        #pragma unroll
        for (int m = 1; m < 8; m <<= 1) vq += __shfl_xor_sync(0xffffffffu, vq, m, 8);
        float vinv = rsqrtf(vq * (1.f / 64.f) + 1e-5f);
        if (valid) {
            #pragma unroll
            for (int t = 0; t < 8; t++) {
                int c = j + t * 8; float g = __ldg(g_v_n + c);
                #pragma unroll
                for (int d = 0; d < 3; d++)
                    g_nodeN[n * FSZ + 128 + c * 3 + d] = vr[t][d] * vinv * g;
            }
        }
    }
    __syncthreads();

    {   // residual scalars
        int tc = tid & 31, te = tid >> 5;
        int c0 = tc * 4;
        float acc[4][4] = {};
        for (int k = 0; k < 128; k++) {
            float4 w = __ldg(reinterpret_cast<const float4*>(&Wr_s[k * 128 + c0]));
            #pragma unroll
            for (int i = 0; i < 4; i++) {
                float a = rs_raw[(te * 4 + i) * 128 + k];
                acc[i][0] += a * w.x; acc[i][1] += a * w.y;
                acc[i][2] += a * w.z; acc[i][3] += a * w.w;
            }
        }
        #pragma unroll
        for (int i = 0; i < 4; i++) {
            int nn = blockIdx.x * TE + te * 4 + i;
            if (nn < N) {
                #pragma unroll
                for (int u = 0; u < 4; u++) out[(long)nn * FSZ + c0 + u] = acc[i][u];
            }
        }
    }
    {   // residual vectors
        int tf = tid & 31, te = tid >> 5;
        int f0 = tf * 2;
        float acc[4][2][3] = {};
        for (int c = 0; c < 64; c++) {
            float2 w = __ldg(reinterpret_cast<const float2*>(&Wr_v[c * 64 + f0]));
            #pragma unroll
            for (int i = 0; i < 4; i++) {
                int ee = te * 4 + i;
                #pragma unroll
                for (int d = 0; d < 3; d++) {
                    float v = rv_raw[(d * TE + ee) * 64 + c];
                    acc[i][0][d] += v * w.x; acc[i][1][d] += v * w.y;
                }
            }
        }
        #pragma unroll
        for (int i = 0; i < 4; i++) {
            int nn = blockIdx.x * TE + te * 4 + i;
            if (nn < N) {
                #pragma unroll
                for (int u = 0; u < 2; u++)
                    #pragma unroll
                    for (int d = 0; d < 3; d++)
                        out[(long)nn * FSZ + 128 + (f0 + u) * 3 + d] = acc[i][u][d];
            }
        }
    }
}

// ---------------------------------------------------------------------------
// Kernel B: fused per-edge pipeline, 32 edges/CTA, 512 threads, f32x2 math.
// smem (floats), all activation arrays k-major with edge index fastest:
//   S2  [0,8192)      : S2[k*32+e], k<256            (aliased by WWe after phase 2)
//   V   [8192,20480)  : V[(d*128+c)*32+e]
//   CR  [20480,32768) : cross, same layout
//   DV  [32768,36864) : DV[c*32+e], c<128
//   OG  [36864,43008) : OG[m*32+e], m<192 (silu s | gates)
//   VP  [43008,49152) : VP[(d*64+f)*32+e]
//   SH  [49152,49280) : SH[q*32+e], q<4
//   EC/AE ints after
//   WWe alias of S2   : WWe[e*192+m]  (env weights, per-edge rows)
#define SMEM_FLOATS 49280
#define SMEM_BYTES  (SMEM_FLOATS * 4 + 2 * TE * 4)

__global__ __launch_bounds__(512, 1) void edge_kernel(
    const float* __restrict__ latents,
    const float* __restrict__ ef,
    const float* __restrict__ esh,
    const int*  __restrict__ edge_index,
    const int*  __restrict__ active_edges,
    const float* __restrict__ g_s_e, const float* __restrict__ b_s_e,
    const float* __restrict__ g_v_e,
    const float* __restrict__ W_ss0, const float* __restrict__ W_vv0,
    const float* __restrict__ W_sv1, const float* __restrict__ W_vs1,
    const float* __restrict__ W_vv1,
    const float* __restrict__ Wp_s,  const float* __restrict__ Wp_v,
    const float* __restrict__ W_env,
    float* __restrict__ out, int EA)
{
    extern __shared__ float sm[];
    float* S2 = sm;
    float* V  = sm + 8192;
    float* CR = sm + 20480;
    float* DV = sm + 32768;
    float* OG = sm + 36864;
    float* VP = sm + 43008;
    float* SH = sm + 49152;
    int*   EC = (int*)(sm + SMEM_FLOATS);
    int*   AE = EC + TE;
    float* WWe = S2;   // alias, live from phase 3 on

    int tid = threadIdx.x;

    // ---------------- Phase 0: LN + gather + dot/cross (16 threads/edge) -----
    {
        int e = tid >> 4, j = tid & 15;
        long i = (long)blockIdx.x * TE + e;
        bool valid = i < EA;
        int ae = 0, n = 0;
        if (valid) { ae = active_edges[i]; n = edge_index[ae]; }
        if (j == 0) {
            EC[e] = valid ? n : -1;
            AE[e] = ae;
            #pragma unroll
            for (int q = 0; q < 4; q++) SH[q * 32 + e] = valid ? esh[i * 4 + q] : 0.f;
        }
        float s1x = 0.f, s1y = 0.f, s1z = 0.f;
        if (valid) { s1x = esh[i*4+1]; s1y = esh[i*4+2]; s1z = esh[i*4+3]; }

        // edge scalar LN
        float xr[8]; float sum = 0.f, sq = 0.f;
        #pragma unroll
        for (int t = 0; t < 8; t++) {
            int k = j + t * 16;
            float x = valid ? ef[i * FSZ + k] : 0.f;
            xr[t] = x; sum += x; sq += x * x;
        }
        #pragma unroll
        for (int m = 1; m < 16; m <<= 1) {
            sum += __shfl_xor_sync(0xffffffffu, sum, m, 16);
            sq  += __shfl_xor_sync(0xffffffffu, sq,  m, 16);
        }
        float mu  = sum * (1.f / 128.f);
        float var = sq * (1.f / 128.f) - mu * mu;
        float inv = rsqrtf(var + 1e-5f);
        #pragma unroll
        for (int t = 0; t < 8; t++) {
            int k = j + t * 16;
            float v = (xr[t] - mu) * inv * __ldg(g_s_e + k) + __ldg(b_s_e + k);
            S2[(128 + k) * 32 + e] = valid ? v : 0.f;
        }
        // node scalar gather
        #pragma unroll
        for (int t = 0; t < 8; t++) {
            int k = j + t * 16;
            S2[k * 32 + e] = valid ? __ldg(&g_nodeN[(long)n * FSZ + k]) : 0.f;
        }
        // edge vector LN
        float ve[4][3]; float vq = 0.f;
        #pragma unroll
        for (int t = 0; t < 4; t++) {
            int c = j + t * 16;
            #pragma unroll
            for (int d = 0; d < 3; d++) {
                float x = valid ? ef[i * FSZ + 128 + c * 3 + d] : 0.f;
                ve[t][d] = x; vq += x * x;
            }
        }
        #pragma unroll
        for (int m = 1; m < 16; m <<= 1) vq += __shfl_xor_sync(0xffffffffu, vq, m, 16);
        float vinv = rsqrtf(vq * (1.f / 64.f) + 1e-5f);
        #pragma unroll
        for (int t = 0; t < 4; t++) {
            int c = j + t * 16; float g = __ldg(g_v_e + c);
            #pragma unroll
            for (int d = 0; d < 3; d++) {
                ve[t][d] = valid ? ve[t][d] * vinv * g : 0.f;
                V[(d * 128 + 64 + c) * 32 + e] = ve[t][d];
            }
        }
        // node vector gather
        float vn[4][3];
        #pragma unroll
        for (int t = 0; t < 4; t++) {
            int c = j + t * 16;
            #pragma unroll
            for (int d = 0; d < 3; d++) {
                vn[t][d] = valid ? __ldg(&g_nodeN[(long)n * FSZ + 128 + c * 3 + d]) : 0.f;
                V[(d * 128 + c) * 32 + e] = vn[t][d];
            }
        }
        // dot / cross from registers
        const float ISQ3 = 0.5773502691896258f, ISQ2 = 0.7071067811865476f;
        #pragma unroll
        for (int t = 0; t < 4; t++) {
            int c = j + t * 16;
            // node channel c
            DV[c * 32 + e] = (vn[t][0]*s1x + vn[t][1]*s1y + vn[t][2]*s1z) * ISQ3;
            CR[(0 * 128 + c) * 32 + e] = (vn[t][1]*s1z - vn[t][2]*s1y) * ISQ2;
            CR[(1 * 128 + c) * 32 + e] = (vn[t][2]*s1x - vn[t][0]*s1z) * ISQ2;
            CR[(2 * 128 + c) * 32 + e] = (vn[t][0]*s1y - vn[t][1]*s1x) * ISQ2;
            // edge channel 64+c
            int cc = 64 + c;
            DV[cc * 32 + e] = (ve[t][0]*s1x + ve[t][1]*s1y + ve[t][2]*s1z) * ISQ3;
            CR[(0 * 128 + cc) * 32 + e] = (ve[t][1]*s1z - ve[t][2]*s1y) * ISQ2;
            CR[(1 * 128 + cc) * 32 + e] = (ve[t][2]*s1x - ve[t][0]*s1z) * ISQ2;
            CR[(2 * 128 + cc) * 32 + e] = (ve[t][0]*s1y - ve[t][1]*s1x) * ISQ2;
        }
    }
    __syncthreads();

    // ---------------- Phase 1: out0 = (S@W_ss0)*sh0 + DV@W_vv0 ; silu/sigmoid
    {
        int tc = tid & 31, tg = tid >> 5;
        int c0 = tc * 6, e0 = tg * 2;
        ull acc[2][3] = {};                 // [edge][colpair]
        #pragma unroll 4
        for (int k = 0; k < 256; k++) {
            float2 av = *reinterpret_cast<const float2*>(&S2[k * 32 + e0]);
            ull a0 = pk2(av.x, av.x), a1 = pk2(av.y, av.y);
            const ull* wp = reinterpret_cast<const ull*>(&W_ss0[k * 192 + c0]);
            ull b0 = __ldg(wp), b1 = __ldg(wp + 1), b2 = __ldg(wp + 2);
            fma2(acc[0][0], a0, b0); fma2(acc[0][1], a0, b1); fma2(acc[0][2], a0, b2);
            fma2(acc[1][0], a1, b0); fma2(acc[1][1], a1, b1); fma2(acc[1][2], a1, b2);
        }
        {   // scale by sh0 (per edge)
            float2 s0v = *reinterpret_cast<const float2*>(&SH[0 * 32 + e0]);
            ull s00 = pk2(s0v.x, s0v.x), s01 = pk2(s0v.y, s0v.y);
            #pragma unroll
            for (int u = 0; u < 3; u++) {
                acc[0][u] = mul2(acc[0][u], s00);
                acc[1][u] = mul2(acc[1][u], s01);
            }
        }
        #pragma unroll 4
        for (int k = 0; k < 128; k++) {
            float2 av = *reinterpret_cast<const float2*>(&DV[k * 32 + e0]);
            ull a0 = pk2(av.x, av.x), a1 = pk2(av.y, av.y);
            const ull* wp = reinterpret_cast<const ull*>(&W_vv0[k * 192 + c0]);
            ull b0 = __ldg(wp), b1 = __ldg(wp + 1), b2 = __ldg(wp + 2);
            fma2(acc[0][0], a0, b0); fma2(acc[0][1], a0, b1); fma2(acc[0][2], a0, b2);
            fma2(acc[1][0], a1, b0); fma2(acc[1][1], a1, b1); fma2(acc[1][2], a1, b2);
        }
        #pragma unroll
        for (int i2 = 0; i2 < 2; i2++) {
            int e = e0 + i2;
            #pragma unroll
            for (int u = 0; u < 3; u++) {
                float x0, x1; upk2(acc[i2][u], x0, x1);
                int m0 = c0 + 2 * u;
                float sg0 = 1.f / (1.f + __expf(-x0));
                float sg1 = 1.f / (1.f + __expf(-x1));
                OG[(m0    ) * 32 + e] = (m0     < 128) ? x0 * sg0 : sg0;
                OG[(m0 + 1) * 32 + e] = (m0 + 1 < 128) ? x1 * sg1 : sg1;
            }
        }
    }
    __syncthreads();

    // ---------------- Phase 2: out_v, gate -> VP (edge-pair packed) ----------
    {
        int tf = tid & 31, tg = tid >> 5;
        int f0 = tf * 2, e0 = tg * 2;
        ull aS0 = 0, aS1 = 0;               // f0, f0+1 — packed across edges
        #pragma unroll 4
        for (int k = 0; k < 256; k++) {
            ull ap = *reinterpret_cast<const ull*>(&S2[k * 32 + e0]);
            float2 w = __ldg(reinterpret_cast<const float2*>(&W_sv1[k * 64 + f0]));
            fma2(aS0, ap, pk2(w.x, w.x));
            fma2(aS1, ap, pk2(w.y, w.y));
        }
        ull aV[2][3] = {}, aC[2][3] = {};
        #pragma unroll 2
        for (int c = 0; c < 128; c++) {
            ull vx = *reinterpret_cast<const ull*>(&V[(0 * 128 + c) * 32 + e0]);
            ull vy = *reinterpret_cast<const ull*>(&V[(1 * 128 + c) * 32 + e0]);
            ull vz = *reinterpret_cast<const ull*>(&V[(2 * 128 + c) * 32 + e0]);
            ull cx = *reinterpret_cast<const ull*>(&CR[(0 * 128 + c) * 32 + e0]);
            ull cy = *reinterpret_cast<const ull*>(&CR[(1 * 128 + c) * 32 + e0]);
            ull cz = *reinterpret_cast<const ull*>(&CR[(2 * 128 + c) * 32 + e0]);
            float2 wv = __ldg(reinterpret_cast<const float2*>(&W_vs1[c * 64 + f0]));
            float2 wc = __ldg(reinterpret_cast<const float2*>(&W_vv1[c * 64 + f0]));
            ull wv0 = pk2(wv.x, wv.x), wv1 = pk2(wv.y, wv.y);
            ull wc0 = pk2(wc.x, wc.x), wc1 = pk2(wc.y, wc.y);
            fma2(aV[0][0], vx, wv0); fma2(aV[0][1], vy, wv0); fma2(aV[0][2], vz, wv0);
            fma2(aV[1][0], vx, wv1); fma2(aV[1][1], vy, wv1); fma2(aV[1][2], vz, wv1);
            fma2(aC[0][0], cx, wc0); fma2(aC[0][1], cy, wc0); fma2(aC[0][2], cz, wc0);
            fma2(aC[1][0], cx, wc1); fma2(aC[1][1], cy, wc1); fma2(aC[1][2], cz, wc1);
        }
        ull s0p = *reinterpret_cast<const ull*>(&SH[0 * 32 + e0]);
        ull s1p[3];
        #pragma unroll
        for (int d = 0; d < 3; d++)
            s1p[d] = *reinterpret_cast<const ull*>(&SH[(1 + d) * 32 + e0]);
        #pragma unroll
        for (int u = 0; u < 2; u++) {
            ull g = *reinterpret_cast<const ull*>(&OG[(128 + f0 + u) * 32 + e0]);
            ull aSu = (u == 0) ? aS0 : aS1;
            #pragma unroll
            for (int d = 0; d < 3; d++) {
                ull t = fma2v(aV[u][d], s0p, aC[u][d]);
                t = fma2v(aSu, s1p[d], t);
                t = mul2(t, g);
                *reinterpret_cast<ull*>(&VP[(d * 64 + f0 + u) * 32 + e0]) = t;
            }
        }
    }
    __syncthreads();

    // ---------------- Phase 3: w = latents[ae] @ W_env -> WWe (aliases S2) ---
    {
        int tc = tid & 31, tg = tid >> 5;
        int c0 = tc * 6, e0 = tg * 2;
        int a0 = AE[e0], a1 = AE[e0 + 1];
        ull acc[2][3] = {};                 // [edge][colpair]
        #pragma unroll 4
        for (int k = 0; k < 64; k++) {
            float l0 = __ldg(&latents[(long)a0 * 64 + k]);
            float l1 = __ldg(&latents[(long)a1 * 64 + k]);
            ull p0 = pk2(l0, l0), p1 = pk2(l1, l1);
            const ull* wp = reinterpret_cast<const ull*>(&W_env[k * 192 + c0]);
            ull b0 = __ldg(wp), b1 = __ldg(wp + 1), b2 = __ldg(wp + 2);
            fma2(acc[0][0], p0, b0); fma2(acc[0][1], p0, b1); fma2(acc[0][2], p0, b2);
            fma2(acc[1][0], p1, b0); fma2(acc[1][1], p1, b1); fma2(acc[1][2], p1, b2);
        }
        #pragma unroll
        for (int i2 = 0; i2 < 2; i2++)
            #pragma unroll
            for (int u = 0; u < 3; u++)
                *reinterpret_cast<ull*>(&WWe[(e0 + i2) * 192 + c0 + 2 * u]) = acc[i2][u];
    }
    __syncthreads();

    // ---------------- Phase 4a: s = (sact@Wp_s)*w_s*0.25 -> atomicAdd --------
    {
        int tc = tid & 31, tg = tid >> 5;
        int c0 = tc * 4, e0 = tg * 2;
        ull acc[2][2] = {};                 // [edge][colpair]
        #pragma unroll 4
        for (int k = 0; k < 128; k++) {
            float2 av = *reinterpret_cast<const float2*>(&OG[k * 32 + e0]);
            ull a0 = pk2(av.x, av.x), a1 = pk2(av.y, av.y);
            const ull* wp = reinterpret_cast<const ull*>(&Wp_s[k * 128 + c0]);
            ull b0 = __ldg(wp), b1 = __ldg(wp + 1);
            fma2(acc[0][0], a0, b0); fma2(acc[0][1], a0, b1);
            fma2(acc[1][0], a1, b0); fma2(acc[1][1], a1, b1);
        }
        const ull QQ = pk2(0.25f, 0.25f);
        #pragma unroll
        for (int i2 = 0; i2 < 2; i2++) {
            int e = e0 + i2; int n = EC[e];
            if (n >= 0) {
                #pragma unroll
                for (int u = 0; u < 2; u++) {
                    ull ww = *reinterpret_cast<const ull*>(&WWe[e * 192 + c0 + 2 * u]);
                    ull val = mul2(mul2(acc[i2][u], ww), QQ);
                    float x0, x1; upk2(val, x0, x1);
                    atomicAdd(&out[(long)n * FSZ + c0 + 2 * u    ], x0);
                    atomicAdd(&out[(long)n * FSZ + c0 + 2 * u + 1], x1);
                }
            }
        }
    }
    // ---------------- Phase 4b: v = (VP@Wp_v)*w_v*0.25 -> atomicAdd ----------
    {
        int tf = tid & 31, tg = tid >> 5;
        int f0 = tf * 2, e0 = tg * 2;
        ull a[2][3] = {};                   // [fcol][d] — packed across edges
        #pragma unroll 2
        for (int c = 0; c < 64; c++) {
            ull v0 = *reinterpret_cast<const ull*>(&VP[(0 * 64 + c) * 32 + e0]);
            ull v1 = *reinterpret_cast<const ull*>(&VP[(1 * 64 + c) * 32 + e0]);
            ull v2 = *reinterpret_cast<const ull*>(&VP[(2 * 64 + c) * 32 + e0]);
            float2 w = __ldg(reinterpret_cast<const float2*>(&Wp_v[c * 64 + f0]));
            ull w0 = pk2(w.x, w.x), w1 = pk2(w.y, w.y);
            fma2(a[0][0], v0, w0); fma2(a[0][1], v1, w0); fma2(a[0][2], v2, w0);
            fma2(a[1][0], v0, w1); fma2(a[1][1], v1, w1); fma2(a[1][2], v2, w1);
        }
        int n0 = EC[e0], n1 = EC[e0 + 1];
        #pragma unroll
        for (int u = 0; u < 2; u++) {
            float ww0 = WWe[ e0      * 192 + 128 + f0 + u] * 0.25f;
            float ww1 = WWe[(e0 + 1) * 192 + 128 + f0 + u] * 0.25f;
            #pragma unroll
            for (int d = 0; d < 3; d++) {
                float x0, x1; upk2(a[u][d], x0, x1);
                if (n0 >= 0) atomicAdd(&out[(long)n0 * FSZ + 128 + (f0 + u) * 3 + d], x0 * ww0);
                if (n1 >= 0) atomicAdd(&out[(long)n1 * FSZ + 128 + (f0 + u) * 3 + d], x1 * ww1);
            }
        }
    }
}

// ---------------------------------------------------------------------------
extern "C" void kernel_launch(void* const* d_in, const int* in_sizes, int n_in,
                              void* d_out, int out_size)
{
    const float* latents = (const float*)d_in[0];
    const float* nodef   = (const float*)d_in[1];
    const float* edgef   = (const float*)d_in[2];
    const float* esh     = (const float*)d_in[3];
    const int*   eidx    = (const int*)  d_in[4];
    // d_in[5] = atom_type (unused)
    const int*   act     = (const int*)  d_in[6];
    const float* g_s_n   = (const float*)d_in[7];
    const float* b_s_n   = (const float*)d_in[8];
    const float* g_v_n   = (const float*)d_in[9];
    const float* g_s_e   = (const float*)d_in[10];
    const float* b_s_e   = (const float*)d_in[11];
    const float* g_v_e   = (const float*)d_in[12];
    const float* W_ss0   = (const float*)d_in[13];
    const float* W_vv0   = (const float*)d_in[14];
    const float* W_sv1   = (const float*)d_in[15];
    const float* W_vs1   = (const float*)d_in[16];
    const float* W_vv1   = (const float*)d_in[17];
    const float* Wp_s    = (const float*)d_in[18];
    const float* Wp_v    = (const float*)d_in[19];
    const float* W_env   = (const float*)d_in[20];
    const float* Wr_s    = (const float*)d_in[21];
    const float* Wr_v    = (const float*)d_in[22];
    float* out = (float*)d_out;

    int N  = in_sizes[1] / FSZ;
    int EA = in_sizes[6];

    cudaFuncSetAttribute(edge_kernel, cudaFuncAttributeMaxDynamicSharedMemorySize,
                         SMEM_BYTES);

    node_kernel<<<(N + TE - 1) / TE, 256>>>(nodef, g_s_n, b_s_n, g_v_n,
                                            Wr_s, Wr_v, out, N);
    edge_kernel<<<(EA + TE - 1) / TE, 512, SMEM_BYTES>>>(
        latents, edgef, esh, eidx, act,
        g_s_e, b_s_e, g_v_e,
        W_ss0, W_vv0, W_sv1, W_vs1, W_vv1,
        Wp_s, Wp_v, W_env, out, EA);
}

// round 5
// speedup vs baseline: 1.2577x; 1.1158x over previous
#include <cuda_runtime.h>
#include <math.h>

#define NS 128
#define NV 64
#define FSZ 320            // NS + 3*NV
#define TE 32              // edges per block

typedef unsigned long long ull;

__device__ __forceinline__ ull pk2(float lo, float hi) {
    ull r; asm("mov.b64 %0,{%1,%2};" : "=l"(r) : "f"(lo), "f"(hi)); return r;
}
__device__ __forceinline__ void upk2(ull v, float& lo, float& hi) {
    asm("mov.b64 {%0,%1},%2;" : "=f"(lo), "=f"(hi) : "l"(v));
}
__device__ __forceinline__ void fma2(ull& d, ull a, ull b) {
    asm("fma.rn.f32x2 %0,%1,%2,%0;" : "+l"(d) : "l"(a), "l"(b));
}
__device__ __forceinline__ ull fma2v(ull a, ull b, ull c) {
    ull d; asm("fma.rn.f32x2 %0,%1,%2,%3;" : "=l"(d) : "l"(a), "l"(b), "l"(c)); return d;
}
__device__ __forceinline__ ull mul2(ull a, ull b) {
    ull d; asm("mul.rn.f32x2 %0,%1,%2;" : "=l"(d) : "l"(a), "l"(b)); return d;
}
// bank-conflict-avoiding smem index: pairs (even e) stay adjacent & 8B aligned
__device__ __forceinline__ int swz(int idx, int e) {
    return idx * 32 + (e ^ ((idx & 15) << 1));
}

// LN'd node features scratch
__device__ float g_nodeN[16000 * FSZ];

// ---------------------------------------------------------------------------
// Kernel A: per-node separable LN -> g_nodeN, residual -> out
// ---------------------------------------------------------------------------
__global__ __launch_bounds__(256) void node_kernel(
    const float* __restrict__ nf,
    const float* __restrict__ g_s_n, const float* __restrict__ b_s_n,
    const float* __restrict__ g_v_n,
    const float* __restrict__ Wr_s, const float* __restrict__ Wr_v,
    float* __restrict__ out, int N)
{
    __shared__ float rs_raw[TE * 128];
    __shared__ float rv_raw[3 * TE * 64];

    int tid = threadIdx.x;
    {
        int e = tid >> 3, j = tid & 7;
        int n = blockIdx.x * TE + e;
        bool valid = n < N;

        float xr[16]; float sum = 0.f, sq = 0.f;
        #pragma unroll
        for (int t = 0; t < 16; t++) {
            int k = j + t * 8;
            float x = valid ? nf[n * FSZ + k] : 0.f;
            xr[t] = x; rs_raw[e * 128 + k] = x;
            sum += x; sq += x * x;
        }
        #pragma unroll
        for (int m = 1; m < 8; m <<= 1) {
            sum += __shfl_xor_sync(0xffffffffu, sum, m, 8);
            sq  += __shfl_xor_sync(0xffffffffu, sq,  m, 8);
        }
        float mu  = sum * (1.f / 128.f);
        float var = sq * (1.f / 128.f) - mu * mu;
        float inv = rsqrtf(var + 1e-5f);
        if (valid) {
            #pragma unroll
            for (int t = 0; t < 16; t++) {
                int k = j + t * 8;
                g_nodeN[n * FSZ + k] = (xr[t] - mu) * inv * __ldg(g_s_n + k) + __ldg(b_s_n + k);
            }
        }
        float vr[8][3]; float vq = 0.f;
        #pragma unroll
        for (int t = 0; t < 8; t++) {
            int c = j + t * 8;
            #pragma unroll
            for (int d = 0; d < 3; d++) {
                float x = valid ? nf[n * FSZ + 128 + c * 3 + d] : 0.f;
                vr[t][d] = x; rv_raw[(d * TE + e) * 64 + c] = x;
                vq += x * x;
            }
        }
        #pragma unroll
        for (int m = 1; m < 8; m <<= 1) vq += __shfl_xor_sync(0xffffffffu, vq, m, 8);
        float vinv = rsqrtf(vq * (1.f / 64.f) + 1e-5f);
        if (valid) {
            #pragma unroll
            for (int t = 0; t < 8; t++) {
                int c = j + t * 8; float g = __ldg(g_v_n + c);
                #pragma unroll
                for (int d = 0; d < 3; d++)
                    g_nodeN[n * FSZ + 128 + c * 3 + d] = vr[t][d] * vinv * g;
            }
        }
    }
    __syncthreads();

    {   // residual scalars
        int tc = tid & 31, te = tid >> 5;
        int c0 = tc * 4;
        float acc[4][4] = {};
        for (int k = 0; k < 128; k++) {
            float4 w = __ldg(reinterpret_cast<const float4*>(&Wr_s[k * 128 + c0]));
            #pragma unroll
            for (int i = 0; i < 4; i++) {
                float a = rs_raw[(te * 4 + i) * 128 + k];
                acc[i][0] += a * w.x; acc[i][1] += a * w.y;
                acc[i][2] += a * w.z; acc[i][3] += a * w.w;
            }
        }
        #pragma unroll
        for (int i = 0; i < 4; i++) {
            int nn = blockIdx.x * TE + te * 4 + i;
            if (nn < N) {
                #pragma unroll
                for (int u = 0; u < 4; u++) out[(long)nn * FSZ + c0 + u] = acc[i][u];
            }
        }
    }
    {   // residual vectors
        int tf = tid & 31, te = tid >> 5;
        int f0 = tf * 2;
        float acc[4][2][3] = {};
        for (int c = 0; c < 64; c++) {
            float2 w = __ldg(reinterpret_cast<const float2*>(&Wr_v[c * 64 + f0]));
            #pragma unroll
            for (int i = 0; i < 4; i++) {
                int ee = te * 4 + i;
                #pragma unroll
                for (int d = 0; d < 3; d++) {
                    float v = rv_raw[(d * TE + ee) * 64 + c];
                    acc[i][0][d] += v * w.x; acc[i][1][d] += v * w.y;
                }
            }
        }
        #pragma unroll
        for (int i = 0; i < 4; i++) {
            int nn = blockIdx.x * TE + te * 4 + i;
            if (nn < N) {
                #pragma unroll
                for (int u = 0; u < 2; u++)
                    #pragma unroll
                    for (int d = 0; d < 3; d++)
                        out[(long)nn * FSZ + 128 + (f0 + u) * 3 + d] = acc[i][u][d];
            }
        }
    }
}

// ---------------------------------------------------------------------------
// Kernel B: fused per-edge pipeline, 32 edges/CTA, 256 threads, 2 CTAs/SM.
// smem (floats), swizzled edge-minor layout via swz():
//   S2 [0,8192)      : S2[swz(k,e)], k<256         (aliased by WWe from ph3)
//   V  [8192,20480)  : V[swz(d*128+c, e)]          (aliased by VP from ph2-end)
//   OG [20480,26624) : OG[swz(m,e)], m<192
//   SH [26624,26752) : SH[q*32+e]
//   EC/AE ints after
#define SMEM_FLOATS 26816
#define SMEM_BYTES  (SMEM_FLOATS * 4 + 256)

__global__ __launch_bounds__(256, 2) void edge_kernel(
    const float* __restrict__ latents,
    const float* __restrict__ ef,
    const float* __restrict__ esh,
    const int*  __restrict__ edge_index,
    const int*  __restrict__ active_edges,
    const float* __restrict__ g_s_e, const float* __restrict__ b_s_e,
    const float* __restrict__ g_v_e,
    const float* __restrict__ W_ss0, const float* __restrict__ W_vv0,
    const float* __restrict__ W_sv1, const float* __restrict__ W_vs1,
    const float* __restrict__ W_vv1,
    const float* __restrict__ Wp_s,  const float* __restrict__ Wp_v,
    const float* __restrict__ W_env,
    float* __restrict__ out, int EA)
{
    extern __shared__ float sm[];
    float* S2 = sm;              // 8192
    float* Vf = sm + 8192;       // 12288
    float* OG = sm + 20480;      // 6144
    float* SHf = sm + 26624;     // 128
    int*   EC = (int*)(sm + 26752);
    int*   AE = EC + TE;
    float* WWe = S2;             // alias: env weights (x0.25) rows [e][192], ph3+
    float* VPb = Vf;             // alias: gated out_v, ph2-end+

    int tid = threadIdx.x;
    const float ISQ3 = 0.5773502691896258f, ISQ2 = 0.7071067811865476f;

    // ---------------- Phase 0: LN + gather (8 threads/edge) ------------------
    {
        int e = tid >> 3, j = tid & 7;
        long i = (long)blockIdx.x * TE + e;
        bool valid = i < EA;
        int ae = 0, n = 0;
        if (valid) { ae = active_edges[i]; n = edge_index[ae]; }
        if (j == 0) {
            EC[e] = valid ? n : -1;
            AE[e] = ae;
            #pragma unroll
            for (int q = 0; q < 4; q++) SHf[q * 32 + e] = valid ? esh[i * 4 + q] : 0.f;
        }
        // edge scalar LN
        float xr[16]; float sum = 0.f, sq = 0.f;
        #pragma unroll
        for (int t = 0; t < 16; t++) {
            int k = j + t * 8;
            float x = valid ? ef[i * FSZ + k] : 0.f;
            xr[t] = x; sum += x; sq += x * x;
        }
        #pragma unroll
        for (int m = 1; m < 8; m <<= 1) {
            sum += __shfl_xor_sync(0xffffffffu, sum, m, 8);
            sq  += __shfl_xor_sync(0xffffffffu, sq,  m, 8);
        }
        float mu  = sum * (1.f / 128.f);
        float var = sq * (1.f / 128.f) - mu * mu;
        float inv = rsqrtf(var + 1e-5f);
        #pragma unroll
        for (int t = 0; t < 16; t++) {
            int k = j + t * 8;
            float v = (xr[t] - mu) * inv * __ldg(g_s_e + k) + __ldg(b_s_e + k);
            S2[swz(128 + k, e)] = valid ? v : 0.f;
        }
        // node scalar gather
        #pragma unroll
        for (int t = 0; t < 16; t++) {
            int k = j + t * 8;
            S2[swz(k, e)] = valid ? __ldg(&g_nodeN[(long)n * FSZ + k]) : 0.f;
        }
        // edge vector LN
        float ve[8][3]; float vq = 0.f;
        #pragma unroll
        for (int t = 0; t < 8; t++) {
            int c = j + t * 8;
            #pragma unroll
            for (int d = 0; d < 3; d++) {
                float x = valid ? ef[i * FSZ + 128 + c * 3 + d] : 0.f;
                ve[t][d] = x; vq += x * x;
            }
        }
        #pragma unroll
        for (int m = 1; m < 8; m <<= 1) vq += __shfl_xor_sync(0xffffffffu, vq, m, 8);
        float vinv = rsqrtf(vq * (1.f / 64.f) + 1e-5f);
        #pragma unroll
        for (int t = 0; t < 8; t++) {
            int c = j + t * 8; float g = __ldg(g_v_e + c);
            #pragma unroll
            for (int d = 0; d < 3; d++)
                Vf[swz(d * 128 + 64 + c, e)] = valid ? ve[t][d] * vinv * g : 0.f;
        }
        // node vector gather
        #pragma unroll
        for (int t = 0; t < 8; t++) {
            int c = j + t * 8;
            #pragma unroll
            for (int d = 0; d < 3; d++)
                Vf[swz(d * 128 + c, e)] = valid ? __ldg(&g_nodeN[(long)n * FSZ + 128 + c * 3 + d]) : 0.f;
        }
    }
    __syncthreads();

    // ---------------- Phase 1: out0 = (S@W_ss0)*sh0 + dot(V,sh1)/√3 @ W_vv0 --
    {
        int tc = tid & 31, tg = tid >> 5;
        int c0 = tc * 6, e0 = tg * 4;
        ull acc[4][3] = {};
        #pragma unroll 4
        for (int k = 0; k < 256; k++) {
            ull apA = *reinterpret_cast<const ull*>(&S2[swz(k, e0)]);
            ull apB = *reinterpret_cast<const ull*>(&S2[swz(k, e0 + 2)]);
            float a0, a1, a2, a3; upk2(apA, a0, a1); upk2(apB, a2, a3);
            const ull* wp = reinterpret_cast<const ull*>(&W_ss0[k * 192 + c0]);
            ull b0 = __ldg(wp), b1 = __ldg(wp + 1), b2 = __ldg(wp + 2);
            ull p0 = pk2(a0, a0), p1 = pk2(a1, a1), p2 = pk2(a2, a2), p3 = pk2(a3, a3);
            fma2(acc[0][0], p0, b0); fma2(acc[0][1], p0, b1); fma2(acc[0][2], p0, b2);
            fma2(acc[1][0], p1, b0); fma2(acc[1][1], p1, b1); fma2(acc[1][2], p1, b2);
            fma2(acc[2][0], p2, b0); fma2(acc[2][1], p2, b1); fma2(acc[2][2], p2, b2);
            fma2(acc[3][0], p3, b0); fma2(acc[3][1], p3, b1); fma2(acc[3][2], p3, b2);
        }
        #pragma unroll
        for (int i = 0; i < 4; i++) {
            float s0 = SHf[0 * 32 + e0 + i];
            ull sp = pk2(s0, s0);
            #pragma unroll
            for (int u = 0; u < 3; u++) acc[i][u] = mul2(acc[i][u], sp);
        }
        // dot part on-the-fly: qX[d] = sh1 pair * (1/sqrt3)
        const ull Q3 = pk2(ISQ3, ISQ3);
        ull qA[3], qB[3];
        #pragma unroll
        for (int d = 0; d < 3; d++) {
            qA[d] = mul2(*reinterpret_cast<const ull*>(&SHf[(1 + d) * 32 + e0]), Q3);
            qB[d] = mul2(*reinterpret_cast<const ull*>(&SHf[(1 + d) * 32 + e0 + 2]), Q3);
        }
        #pragma unroll 4
        for (int c = 0; c < 128; c++) {
            ull vxA = *reinterpret_cast<const ull*>(&Vf[swz(c, e0)]);
            ull vyA = *reinterpret_cast<const ull*>(&Vf[swz(128 + c, e0)]);
            ull vzA = *reinterpret_cast<const ull*>(&Vf[swz(256 + c, e0)]);
            ull vxB = *reinterpret_cast<const ull*>(&Vf[swz(c, e0 + 2)]);
            ull vyB = *reinterpret_cast<const ull*>(&Vf[swz(128 + c, e0 + 2)]);
            ull vzB = *reinterpret_cast<const ull*>(&Vf[swz(256 + c, e0 + 2)]);
            ull dvA = fma2v(vzA, qA[2], fma2v(vyA, qA[1], mul2(vxA, qA[0])));
            ull dvB = fma2v(vzB, qB[2], fma2v(vyB, qB[1], mul2(vxB, qB[0])));
            float a0, a1, a2, a3; upk2(dvA, a0, a1); upk2(dvB, a2, a3);
            const ull* wp = reinterpret_cast<const ull*>(&W_vv0[c * 192 + c0]);
            ull b0 = __ldg(wp), b1 = __ldg(wp + 1), b2 = __ldg(wp + 2);
            ull p0 = pk2(a0, a0), p1 = pk2(a1, a1), p2 = pk2(a2, a2), p3 = pk2(a3, a3);
            fma2(acc[0][0], p0, b0); fma2(acc[0][1], p0, b1); fma2(acc[0][2], p0, b2);
            fma2(acc[1][0], p1, b0); fma2(acc[1][1], p1, b1); fma2(acc[1][2], p1, b2);
            fma2(acc[2][0], p2, b0); fma2(acc[2][1], p2, b1); fma2(acc[2][2], p2, b2);
            fma2(acc[3][0], p3, b0); fma2(acc[3][1], p3, b1); fma2(acc[3][2], p3, b2);
        }
        // silu / sigmoid
        #pragma unroll
        for (int i = 0; i < 4; i++) {
            int e = e0 + i;
            #pragma unroll
            for (int u = 0; u < 3; u++) {
                float x0, x1; upk2(acc[i][u], x0, x1);
                int m0 = c0 + 2 * u;
                float sg0 = 1.f / (1.f + __expf(-x0));
                float sg1 = 1.f / (1.f + __expf(-x1));
                OG[swz(m0,     e)] = (m0     < 128) ? x0 * sg0 : sg0;
                OG[swz(m0 + 1, e)] = (m0 + 1 < 128) ? x1 * sg1 : sg1;
            }
        }
    }
    __syncthreads();

    // ---------------- Phase 2: out_v (cross folded via linearity), gate ------
    ull vout[2][3][2];   // [u][d][pair] — kept in regs across the barrier
    {
        int tf = tid & 31, tg = tid >> 5;
        int f0 = tf * 2, e0 = tg * 4;
        ull aS[2][2] = {};       // [u][pair]
        #pragma unroll 4
        for (int k = 0; k < 256; k++) {
            ull apA = *reinterpret_cast<const ull*>(&S2[swz(k, e0)]);
            ull apB = *reinterpret_cast<const ull*>(&S2[swz(k, e0 + 2)]);
            float2 w = __ldg(reinterpret_cast<const float2*>(&W_sv1[k * 64 + f0]));
            ull w0 = pk2(w.x, w.x), w1 = pk2(w.y, w.y);
            fma2(aS[0][0], apA, w0); fma2(aS[0][1], apB, w0);
            fma2(aS[1][0], apA, w1); fma2(aS[1][1], apB, w1);
        }
        ull aV[2][3][2] = {}, B[2][3][2] = {};
        #pragma unroll 2
        for (int c = 0; c < 128; c++) {
            ull vA[3], vB[3];
            #pragma unroll
            for (int d = 0; d < 3; d++) {
                vA[d] = *reinterpret_cast<const ull*>(&Vf[swz(d * 128 + c, e0)]);
                vB[d] = *reinterpret_cast<const ull*>(&Vf[swz(d * 128 + c, e0 + 2)]);
            }
            float2 wv = __ldg(reinterpret_cast<const float2*>(&W_vs1[c * 64 + f0]));
            float2 wc = __ldg(reinterpret_cast<const float2*>(&W_vv1[c * 64 + f0]));
            ull wv0 = pk2(wv.x, wv.x), wv1 = pk2(wv.y, wv.y);
            ull wc0 = pk2(wc.x, wc.x), wc1 = pk2(wc.y, wc.y);
            #pragma unroll
            for (int d = 0; d < 3; d++) {
                fma2(aV[0][d][0], vA[d], wv0); fma2(aV[0][d][1], vB[d], wv0);
                fma2(aV[1][d][0], vA[d], wv1); fma2(aV[1][d][1], vB[d], wv1);
                fma2(B[0][d][0],  vA[d], wc0); fma2(B[0][d][1],  vB[d], wc0);
                fma2(B[1][d][0],  vA[d], wc1); fma2(B[1][d][1],  vB[d], wc1);
            }
        }
        // epilogue per pair
        #pragma unroll
        for (int p = 0; p < 2; p++) {
            int ep = e0 + 2 * p;
            ull s0p = *reinterpret_cast<const ull*>(&SHf[0 * 32 + ep]);
            ull s1p[3], c1p[3], c1n[3];
            const ull Q2 = pk2(ISQ2, ISQ2), Q2N = pk2(-ISQ2, -ISQ2);
            #pragma unroll
            for (int d = 0; d < 3; d++) {
                s1p[d] = *reinterpret_cast<const ull*>(&SHf[(1 + d) * 32 + ep]);
                c1p[d] = mul2(s1p[d], Q2);
                c1n[d] = mul2(s1p[d], Q2N);
            }
            #pragma unroll
            for (int u = 0; u < 2; u++) {
                ull g = *reinterpret_cast<const ull*>(&OG[swz(128 + f0 + u, ep)]);
                ull aC[3];
                aC[0] = fma2v(B[u][2][p], c1n[1], mul2(B[u][1][p], c1p[2]));
                aC[1] = fma2v(B[u][0][p], c1n[2], mul2(B[u][2][p], c1p[0]));
                aC[2] = fma2v(B[u][1][p], c1n[0], mul2(B[u][0][p], c1p[1]));
                #pragma unroll
                for (int d = 0; d < 3; d++) {
                    ull t = fma2v(aV[u][d][p], s0p, aC[d]);
                    t = fma2v(aS[u][p], s1p[d], t);
                    vout[u][d][p] = mul2(t, g);
                }
            }
        }
    }
    __syncthreads();   // all V/S2 reads done

    // ---------------- Phase 2b: write VP over V ------------------------------
    {
        int tf = tid & 31, tg = tid >> 5;
        int f0 = tf * 2, e0 = tg * 4;
        #pragma unroll
        for (int u = 0; u < 2; u++)
            #pragma unroll
            for (int d = 0; d < 3; d++) {
                *reinterpret_cast<ull*>(&VPb[swz(d * 64 + f0 + u, e0)])     = vout[u][d][0];
                *reinterpret_cast<ull*>(&VPb[swz(d * 64 + f0 + u, e0 + 2)]) = vout[u][d][1];
            }
    }
    // ---------------- Phase 3: WWe = 0.25 * latents[ae] @ W_env (over S2) ----
    {
        int tc = tid & 31, tg = tid >> 5;
        int c0 = tc * 6, e0 = tg * 4;
        int a_[4];
        #pragma unroll
        for (int i = 0; i < 4; i++) a_[i] = AE[e0 + i];
        ull acc[4][3] = {};
        #pragma unroll 4
        for (int k = 0; k < 64; k++) {
            const ull* wp = reinterpret_cast<const ull*>(&W_env[k * 192 + c0]);
            ull b0 = __ldg(wp), b1 = __ldg(wp + 1), b2 = __ldg(wp + 2);
            #pragma unroll
            for (int i = 0; i < 4; i++) {
                float l = __ldg(&latents[(long)a_[i] * 64 + k]);
                ull p = pk2(l, l);
                fma2(acc[i][0], p, b0); fma2(acc[i][1], p, b1); fma2(acc[i][2], p, b2);
            }
        }
        const ull QQ = pk2(0.25f, 0.25f);
        #pragma unroll
        for (int i = 0; i < 4; i++)
            #pragma unroll
            for (int u = 0; u < 3; u++)
                *reinterpret_cast<ull*>(&WWe[(e0 + i) * 192 + c0 + 2 * u]) = mul2(acc[i][u], QQ);
    }
    __syncthreads();

    // ---------------- Phase 4a: s = (sact@Wp_s)*ww -> atomicAdd --------------
    {
        int tc = tid & 31, tg = tid >> 5;
        int c0 = tc * 4, e0 = tg * 4;
        ull acc[4][2] = {};
        #pragma unroll 4
        for (int k = 0; k < 128; k++) {
            ull apA = *reinterpret_cast<const ull*>(&OG[swz(k, e0)]);
            ull apB = *reinterpret_cast<const ull*>(&OG[swz(k, e0 + 2)]);
            float a0, a1, a2, a3; upk2(apA, a0, a1); upk2(apB, a2, a3);
            const ull* wp = reinterpret_cast<const ull*>(&Wp_s[k * 128 + c0]);
            ull b0 = __ldg(wp), b1 = __ldg(wp + 1);
            ull p0 = pk2(a0, a0), p1 = pk2(a1, a1), p2 = pk2(a2, a2), p3 = pk2(a3, a3);
            fma2(acc[0][0], p0, b0); fma2(acc[0][1], p0, b1);
            fma2(acc[1][0], p1, b0); fma2(acc[1][1], p1, b1);
            fma2(acc[2][0], p2, b0); fma2(acc[2][1], p2, b1);
            fma2(acc[3][0], p3, b0); fma2(acc[3][1], p3, b1);
        }
        #pragma unroll
        for (int i = 0; i < 4; i++) {
            int e = e0 + i; int n = EC[e];
            if (n >= 0) {
                #pragma unroll
                for (int u = 0; u < 2; u++) {
                    ull ww = *reinterpret_cast<const ull*>(&WWe[e * 192 + c0 + 2 * u]);
                    float x0, x1; upk2(mul2(acc[i][u], ww), x0, x1);
                    atomicAdd(&out[(long)n * FSZ + c0 + 2 * u    ], x0);
                    atomicAdd(&out[(long)n * FSZ + c0 + 2 * u + 1], x1);
                }
            }
        }
    }
    // ---------------- Phase 4b: v = (VP@Wp_v)*ww -> atomicAdd ----------------
    {
        int tf = tid & 31, tg = tid >> 5;
        int f0 = tf * 2, e0 = tg * 4;
        ull a[2][3][2] = {};     // [u][d][pair]
        #pragma unroll 2
        for (int c = 0; c < 64; c++) {
            float2 w = __ldg(reinterpret_cast<const float2*>(&Wp_v[c * 64 + f0]));
            ull w0 = pk2(w.x, w.x), w1 = pk2(w.y, w.y);
            #pragma unroll
            for (int d = 0; d < 3; d++) {
                ull vA = *reinterpret_cast<const ull*>(&VPb[swz(d * 64 + c, e0)]);
                ull vB = *reinterpret_cast<const ull*>(&VPb[swz(d * 64 + c, e0 + 2)]);
                fma2(a[0][d][0], vA, w0); fma2(a[0][d][1], vB, w0);
                fma2(a[1][d][0], vA, w1); fma2(a[1][d][1], vB, w1);
            }
        }
        #pragma unroll
        for (int p = 0; p < 2; p++) {
            int ea = e0 + 2 * p, eb = ea + 1;
            int n0 = EC[ea], n1 = EC[eb];
            #pragma unroll
            for (int u = 0; u < 2; u++) {
                float ww0 = WWe[ea * 192 + 128 + f0 + u];
                float ww1 = WWe[eb * 192 + 128 + f0 + u];
                #pragma unroll
                for (int d = 0; d < 3; d++) {
                    float x0, x1; upk2(a[u][d][p], x0, x1);
                    if (n0 >= 0) atomicAdd(&out[(long)n0 * FSZ + 128 + (f0 + u) * 3 + d], x0 * ww0);
                    if (n1 >= 0) atomicAdd(&out[(long)n1 * FSZ + 128 + (f0 + u) * 3 + d], x1 * ww1);
                }
            }
        }
    }
}

// ---------------------------------------------------------------------------
extern "C" void kernel_launch(void* const* d_in, const int* in_sizes, int n_in,
                              void* d_out, int out_size)
{
    const float* latents = (const float*)d_in[0];
    const float* nodef   = (const float*)d_in[1];
    const float* edgef   = (const float*)d_in[2];
    const float* esh     = (const float*)d_in[3];
    const int*   eidx    = (const int*)  d_in[4];
    // d_in[5] = atom_type (unused)
    const int*   act     = (const int*)  d_in[6];
    const float* g_s_n   = (const float*)d_in[7];
    const float* b_s_n   = (const float*)d_in[8];
    const float* g_v_n   = (const float*)d_in[9];
    const float* g_s_e   = (const float*)d_in[10];
    const float* b_s_e   = (const float*)d_in[11];
    const float* g_v_e   = (const float*)d_in[12];
    const float* W_ss0   = (const float*)d_in[13];
    const float* W_vv0   = (const float*)d_in[14];
    const float* W_sv1   = (const float*)d_in[15];
    const float* W_vs1   = (const float*)d_in[16];
    const float* W_vv1   = (const float*)d_in[17];
    const float* Wp_s    = (const float*)d_in[18];
    const float* Wp_v    = (const float*)d_in[19];
    const float* W_env   = (const float*)d_in[20];
    const float* Wr_s    = (const float*)d_in[21];
    const float* Wr_v    = (const float*)d_in[22];
    float* out = (float*)d_out;

    int N  = in_sizes[1] / FSZ;
    int EA = in_sizes[6];

    cudaFuncSetAttribute(edge_kernel, cudaFuncAttributeMaxDynamicSharedMemorySize,
                         SMEM_BYTES);

    node_kernel<<<(N + TE - 1) / TE, 256>>>(nodef, g_s_n, b_s_n, g_v_n,
                                            Wr_s, Wr_v, out, N);
    edge_kernel<<<(EA + TE - 1) / TE, 256, SMEM_BYTES>>>(
        latents, edgef, esh, eidx, act,
        g_s_e, b_s_e, g_v_e,
        W_ss0, W_vv0, W_sv1, W_vs1, W_vv1,
        Wp_s, Wp_v, W_env, out, EA);
}